// round 16
// baseline (speedup 1.0000x reference)
#include <cuda_runtime.h>
#include <math.h>
#include <stdint.h>

#define B 4
#define T 4096
#define S 4096
#define E 512
#define H 64
#define RR 16
#define NN 64
#define QSCALE 0.18033688011112042f

typedef unsigned long long u64;

// ------------------ device scratch ------------------
__device__ float g_V[RR * 64];
__device__ float g_u[B * T];
__device__ float g_k[B * S * H];
__device__ float g_v[B * S * H];
__device__ float g_wq[B * NN];
__device__ float g_op[64 * B * NN * H];
__device__ float g_a[B * NN];

// ------------------ helpers ------------------
__device__ __forceinline__ void ffma2(u64& d, u64 a, u64 b) {
    asm("fma.rn.f32x2 %0, %1, %2, %0;" : "+l"(d) : "l"(a), "l"(b));
}
__device__ __forceinline__ u64 pk2(float x, float y) {
    u64 r; asm("mov.b64 %0, {%1,%2};" : "=l"(r) : "f"(x), "f"(y)); return r;
}
__device__ __forceinline__ float2 up2(u64 v) {
    float2 r; asm("mov.b64 {%0,%1}, %2;" : "=f"(r.x), "=f"(r.y) : "l"(v)); return r;
}
__device__ __forceinline__ float ex2f(float x) {
    float y; asm("ex2.approx.ftz.f32 %0, %1;" : "=f"(y) : "f"(x)); return y;
}

// =============== prep: minmax + cheb coeffs of q (float) + u ===============
__global__ __launch_bounds__(1024) void prep_k(const float* __restrict__ x,
                                               const float* __restrict__ qw,
                                               const float* __restrict__ qb) {
    __shared__ float smn[1024], smx[1024];
    __shared__ float fd[64][17];
    __shared__ float cc[2];
    const int tid = threadIdx.x;
    float mn = 1e30f, mx = -1e30f;
    for (int i = tid; i < B * T; i += 1024) {
        float v = x[i]; mn = fminf(mn, v); mx = fmaxf(mx, v);
    }
    smn[tid] = mn; smx[tid] = mx; __syncthreads();
    for (int o = 512; o > 0; o >>= 1) {
        if (tid < o) { smn[tid] = fminf(smn[tid], smn[tid+o]); smx[tid] = fmaxf(smx[tid], smx[tid+o]); }
        __syncthreads();
    }
    if (tid == 0) {
        cc[0] = 0.5f * (smn[0] + smx[0]);
        cc[1] = 0.5f * (smx[0] - smn[0]) + 1e-6f;
    }
    __syncthreads();
    const float c = cc[0], r = cc[1];
    {
        int h = tid >> 4, j = tid & 15;
        float xx = c + r * cospif((j + 0.5f) / (float)RR);
        fd[h][j] = QSCALE * tanhf(qw[h] * xx + qb[h]);
    }
    __syncthreads();
    {
        int h = tid >> 4, m = tid & 15;
        float a = 0.0f;
        for (int j = 0; j < RR; j++)
            a += fd[h][j] * cospif((float)(m * (2*j + 1)) / (2.0f * RR));
        a *= (m == 0 ? 1.0f : 2.0f) / RR;
        g_V[m * 64 + h] = a;
    }
    for (int i = tid; i < B * T; i += 1024) g_u[i] = (x[i] - c) / r;
}

// =============== moments + quadrature weights (per batch) ===============
__global__ __launch_bounds__(512) void momw_k() {
    __shared__ float sM[NN][17];
    __shared__ float sMM[NN];
    const int b = blockIdx.x, tid = threadIdx.x;
    const int wr = tid >> 5, l = tid & 31;
    float acc[NN];
#pragma unroll
    for (int n = 0; n < NN; n++) acc[n] = 0.0f;
    for (int t = tid; t < T; t += 512) {
        float u = g_u[b*T + t];
        float t0 = 1.0f, t1 = u;
        acc[0] += 1.0f; acc[1] += u;
#pragma unroll
        for (int n = 2; n < NN; n++) {
            float t2 = 2.0f*u*t1 - t0;
            acc[n] += t2;
            t0 = t1; t1 = t2;
        }
    }
#pragma unroll
    for (int n = 0; n < NN; n++) {
        float v = acc[n];
        v += __shfl_xor_sync(0xffffffff, v, 16);
        v += __shfl_xor_sync(0xffffffff, v, 8);
        v += __shfl_xor_sync(0xffffffff, v, 4);
        v += __shfl_xor_sync(0xffffffff, v, 2);
        v += __shfl_xor_sync(0xffffffff, v, 1);
        if (l == 0) sM[n][wr] = v;
    }
    __syncthreads();
    if (tid < NN) {
        float s = 0.0f;
#pragma unroll
        for (int w = 0; w < 16; w++) s += sM[tid][w];
        sMM[tid] = s;
    }
    __syncthreads();
    if (tid < NN) {
        int j = tid;
        float uj = cospif((j + 0.5f) / (float)NN);
        float t0 = 1.0f, t1 = uj;
        float w = sMM[0] * (1.0f/NN) + sMM[1] * t1 * (2.0f/NN);
        for (int n = 2; n < NN; n++) {
            float t2 = 2.0f*uj*t1 - t0;
            w += sMM[n] * t2 * (2.0f/NN);
            t0 = t1; t1 = t2;
        }
        g_wq[b*NN + j] = w;
    }
}

// =============== kv kernel: R8/R14 version (measured 95us three times) ===============
#define KV_EA 0
#define KV_WP (64 * 66)
#define KV_U64 (2 * 64 * 66)
#define KV_SMEM (KV_U64 * 8)

__global__ __launch_bounds__(256, 2) void kv_pk(const float* __restrict__ emb,
                                                const float* __restrict__ kw,
                                                const float* __restrict__ kb,
                                                const float* __restrict__ vw) {
    extern __shared__ __align__(16) u64 sm8[];
    const int r0 = blockIdx.x * 64;
    const int tid = threadIdx.x;
    const int wr = tid >> 5, l = tid & 31;

    u64 acc[8][2] = {};

    for (int e0 = 0; e0 < E; e0 += 64) {
        __syncthreads();
#pragma unroll
        for (int k = 0; k < 4; k++) {
            int idx = k * 256 + tid;
            int r = idx & 63, eg = (idx >> 6) << 2;
            float4 v = *(const float4*)(emb + (size_t)(r0 + r) * E + e0 + eg);
            sm8[KV_EA + (eg+0)*66 + r] = pk2(v.x, v.x);
            sm8[KV_EA + (eg+1)*66 + r] = pk2(v.y, v.y);
            sm8[KV_EA + (eg+2)*66 + r] = pk2(v.z, v.z);
            sm8[KV_EA + (eg+3)*66 + r] = pk2(v.w, v.w);
        }
#pragma unroll
        for (int k = 0; k < 4; k++) {
            int idx = k * 256 + tid;
            int cp = idx & 63, eg = (idx >> 6) << 2;
            const float* w0p;
            const float* w1p;
            if (cp < 32) { w0p = kw + (size_t)(2*cp) * E; w1p = kw + (size_t)(2*cp+1) * E; }
            else         { w0p = vw + (size_t)(2*cp-64) * E; w1p = vw + (size_t)(2*cp-63) * E; }
            float4 a = *(const float4*)(w0p + e0 + eg);
            float4 bq = *(const float4*)(w1p + e0 + eg);
            sm8[KV_WP + (eg+0)*66 + cp] = pk2(a.x, bq.x);
            sm8[KV_WP + (eg+1)*66 + cp] = pk2(a.y, bq.y);
            sm8[KV_WP + (eg+2)*66 + cp] = pk2(a.z, bq.z);
            sm8[KV_WP + (eg+3)*66 + cp] = pk2(a.w, bq.w);
        }
        __syncthreads();
#pragma unroll 8
        for (int e = 0; e < 64; e++) {
            const u64* ap = sm8 + KV_EA + e*66 + 8*wr;
            ulonglong2 a01 = *(const ulonglong2*)(ap + 0);
            ulonglong2 a23 = *(const ulonglong2*)(ap + 2);
            ulonglong2 a45 = *(const ulonglong2*)(ap + 4);
            ulonglong2 a67 = *(const ulonglong2*)(ap + 6);
            u64 ar[8] = {a01.x, a01.y, a23.x, a23.y, a45.x, a45.y, a67.x, a67.y};
            ulonglong2 bb = *(const ulonglong2*)(sm8 + KV_WP + e*66 + 2*l);
#pragma unroll
            for (int j = 0; j < 8; j++) {
                ffma2(acc[j][0], ar[j], bb.x);
                ffma2(acc[j][1], ar[j], bb.y);
            }
        }
    }
    float4 bias = make_float4(0.f, 0.f, 0.f, 0.f);
    if (l < 16) bias = *(const float4*)(kb + 4*l);
#pragma unroll
    for (int j = 0; j < 8; j++) {
        float2 c01 = up2(acc[j][0]);
        float2 c23 = up2(acc[j][1]);
        size_t row = (size_t)r0 + 8*wr + j;
        float4 o;
        if (l < 16) {
            o.x = tanhf(c01.x + bias.x); o.y = tanhf(c01.y + bias.y);
            o.z = tanhf(c23.x + bias.z); o.w = tanhf(c23.y + bias.w);
            *(float4*)(g_k + row * H + 4*l) = o;
        } else {
            o.x = tanhf(c01.x); o.y = tanhf(c01.y);
            o.z = tanhf(c23.x); o.w = tanhf(c23.y);
            *(float4*)(g_v + row * H + 4*l - 64) = o;
        }
    }
}

// =============== fused attention: P -> G -> rd -> o (per 64-s block) ===============
#define AT_KS 0
#define AT_VV 0
#define AT_VS 16896
#define AT_TN 20992
#define AT_PF 25344
#define AT_GP 29696
#define AT_WS 47104
#define AT_RD 47616
#define AT_SMEM 47872

__global__ __launch_bounds__(256) void attn_k() {
    extern __shared__ __align__(16) char smb[];
    float* ks  = (float*)(smb + AT_KS);
    u64*   vv  = (u64*)  (smb + AT_VV);
    float* Vs  = (float*)(smb + AT_VS);
    float* Tn  = (float*)(smb + AT_TN);
    float* Pf  = (float*)(smb + AT_PF);
    u64*   Gp  = (u64*)  (smb + AT_GP);
    u64*   wsd = (u64*)  (smb + AT_WS);
    float* rdf = (float*)(smb + AT_RD);

    const int b = blockIdx.y, sp = blockIdx.x;
    const int s0 = sp * 64;
    const int tid = threadIdx.x, wr = tid >> 5, l = tid & 31;

#pragma unroll
    for (int k = 0; k < 4; k++) Vs[k*256 + tid] = g_V[k*256 + tid];
#pragma unroll
    for (int k = 0; k < 4; k++) {
        int i = k*256 + tid;
        int j = i >> 4, m = i & 15;
        Tn[j*17 + m] = cospif((float)(m * (2*j + 1)) / 128.0f);
    }
    if (tid < 64) {
        float w = g_wq[b*NN + tid];
        wsd[tid] = pk2(w, w);
    }
#pragma unroll
    for (int k = 0; k < 16; k++) {
        int i = k*256 + tid;
        int s = i >> 6, h = i & 63;
        ks[s*65 + h] = g_k[(size_t)(b*S + s0 + s)*H + h];
    }
    __syncthreads();

    {
        int s = tid & 63, mq = tid >> 6;
        float pacc[4] = {};
#pragma unroll
        for (int h = 0; h < 64; h++) {
            float kx = ks[s*65 + h];
#pragma unroll
            for (int mi = 0; mi < 4; mi++) pacc[mi] += Vs[(4*mq + mi)*64 + h] * kx;
        }
#pragma unroll
        for (int mi = 0; mi < 4; mi++) Pf[(4*mq + mi)*68 + s] = pacc[mi];
    }
    __syncthreads();

    {
        int j = tid >> 2, sq = tid & 3;
        u64 am[16];
#pragma unroll
        for (int m = 0; m < 16; m++) {
            float t = Tn[j*17 + m];
            am[m] = pk2(t, t);
        }
#pragma unroll
        for (int i = 0; i < 8; i++) {
            int p = sq + 4*i;
            u64 lacc = 0;
#pragma unroll
            for (int m = 0; m < 16; m++)
                ffma2(lacc, am[m], *(const u64*)&Pf[m*68 + 2*p]);
            float2 f = up2(lacc);
            Gp[j*34 + p] = pk2(ex2f(f.x), ex2f(f.y));
        }
    }
    __syncthreads();

    if (tid < 32) {
        int p = tid;
        u64 dacc = 0;
#pragma unroll
        for (int j = 0; j < 64; j++) ffma2(dacc, wsd[j], Gp[j*34 + p]);
        float2 d2 = up2(dacc);
        rdf[2*p]   = 1.0f / d2.x;
        rdf[2*p+1] = 1.0f / d2.y;
    }
    __syncthreads();

    {
        int p = tid >> 3, hq = tid & 7;
        size_t rv = (size_t)(b*S + s0 + 2*p) * H;
        float rd0 = rdf[2*p], rd1 = rdf[2*p+1];
#pragma unroll
        for (int i = 0; i < 8; i++) {
            int h = hq + 8*i;
            vv[p*66 + h] = pk2(g_v[rv + h] * rd0, g_v[rv + H + h] * rd1);
        }
    }
    __syncthreads();

    u64 acc[8][2] = {};
#pragma unroll 4
    for (int p = 0; p < 32; p++) {
        u64 b0 = vv[p*66 + l];
        u64 b1 = vv[p*66 + 32 + l];
#pragma unroll
        for (int jj = 0; jj < 8; jj++) {
            u64 a = Gp[(8*wr + jj)*34 + p];
            ffma2(acc[jj][0], a, b0);
            ffma2(acc[jj][1], a, b1);
        }
    }
#pragma unroll
    for (int jj = 0; jj < 8; jj++) {
        int j = 8*wr + jj;
        float2 f0 = up2(acc[jj][0]);
        float2 f1 = up2(acc[jj][1]);
        size_t base = ((size_t)(sp*B + b)*NN + j)*H;
        g_op[base + l]      = f0.x + f0.y;
        g_op[base + 32 + l] = f1.x + f1.y;
    }
}

// =============== fused: F at nodes + chebfit (one block per batch) ===============
__global__ __launch_bounds__(256) void ffin_k(const float* __restrict__ pw,
                                              const float* __restrict__ pb) {
    __shared__ float red[NN][5];
    __shared__ float Fv[NN];
    const int b = blockIdx.x, tid = threadIdx.x;
    const int j = tid >> 2, q = tid & 3;
    float p = 0.0f;
    for (int h = q*16; h < q*16 + 16; h++) {
        float o = 0.0f;
#pragma unroll 8
        for (int sp = 0; sp < 64; sp++)
            o += g_op[((size_t)(sp*B + b)*NN + j)*H + h];
        p += tanhf(o) * pw[h];
    }
    red[j][q] = p;
    __syncthreads();
    if (tid < NN) Fv[tid] = pb[0] + red[tid][0] + red[tid][1] + red[tid][2] + red[tid][3];
    __syncthreads();
    if (tid < NN) {
        int n = tid;
        float a = 0.0f;
        for (int j2 = 0; j2 < NN; j2++)
            a += Fv[j2] * cospif((float)(n * (2*j2 + 1)) / (2.0f * NN));
        g_a[b*NN + n] = a * ((n == 0 ? 1.0f : 2.0f) / NN);
    }
}

// =============== out[b,t] = Clenshaw(a, u_t) ===============
__global__ __launch_bounds__(256) void final_eval(float* __restrict__ out) {
    __shared__ float as[B * NN];
    int tid = threadIdx.x;
    as[tid] = g_a[tid];
    __syncthreads();
    int i = blockIdx.x * 256 + tid;
    int b = i >> 12;
    float u = g_u[i];
    const float* a = &as[b * NN];
    float u2 = 2.0f * u;
    float bk1 = 0.0f, bk2 = 0.0f;
#pragma unroll
    for (int n = NN - 1; n >= 1; n--) {
        float bk = a[n] + u2*bk1 - bk2;
        bk2 = bk1; bk1 = bk;
    }
    out[i] = a[0] + u*bk1 - bk2;
}

// ---------------------------------------------------------------------------
extern "C" void kernel_launch(void* const* d_in, const int* in_sizes, int n_in,
                              void* d_out, int out_size) {
    const float* x   = (const float*)d_in[0];
    const float* emb = (const float*)d_in[1];
    const float* kw  = (const float*)d_in[2];
    const float* kb  = (const float*)d_in[3];
    const float* qw  = (const float*)d_in[4];
    const float* qb  = (const float*)d_in[5];
    const float* vw  = (const float*)d_in[6];
    const float* pw  = (const float*)d_in[7];
    const float* pb  = (const float*)d_in[8];
    float* out = (float*)d_out;

    cudaFuncSetAttribute(kv_pk,  cudaFuncAttributeMaxDynamicSharedMemorySize, KV_SMEM);
    cudaFuncSetAttribute(attn_k, cudaFuncAttributeMaxDynamicSharedMemorySize, AT_SMEM);

    prep_k<<<1, 1024>>>(x, qw, qb);
    momw_k<<<B, 512>>>();
    kv_pk<<<(B * S) / 64, 256, KV_SMEM>>>(emb, kw, kb, vw);
    attn_k<<<dim3(64, B), 256, AT_SMEM>>>();
    ffin_k<<<B, 256>>>(pw, pb);
    final_eval<<<(B * T) / 256, 256>>>(out);
}

// round 17
// speedup vs baseline: 1.5249x; 1.5249x over previous
#include <cuda_runtime.h>
#include <math.h>
#include <stdint.h>

#define B 4
#define T 4096
#define S 4096
#define E 512
#define H 64
#define RR 16
#define NN 64
#define QSCALE 0.18033688011112042f

typedef unsigned long long u64;

// ------------------ device scratch ------------------
__device__ float g_V[B * RR * 64];     // per-batch cheb coeffs of q
__device__ float g_u[B * T];
__device__ float g_k[B * S * H];
__device__ float g_v[B * S * H];
__device__ float g_wq[B * NN];
__device__ float g_op[64 * B * NN * H];
__device__ float g_F[B * NN];
__device__ float g_a[B * NN];

// ------------------ helpers ------------------
__device__ __forceinline__ void ffma2(u64& d, u64 a, u64 b) {
    asm("fma.rn.f32x2 %0, %1, %2, %0;" : "+l"(d) : "l"(a), "l"(b));
}
__device__ __forceinline__ u64 pk2(float x, float y) {
    u64 r; asm("mov.b64 %0, {%1,%2};" : "=l"(r) : "f"(x), "f"(y)); return r;
}
__device__ __forceinline__ float2 up2(u64 v) {
    float2 r; asm("mov.b64 {%0,%1}, %2;" : "=f"(r.x), "=f"(r.y) : "l"(v)); return r;
}
__device__ __forceinline__ float ex2f(float x) {
    float y; asm("ex2.approx.ftz.f32 %0, %1;" : "=f"(y) : "f"(x)); return y;
}

// =============== per-batch prep: minmax + coeffs + u + moments + weights ===============
__global__ __launch_bounds__(512) void pm_k(const float* __restrict__ x,
                                            const float* __restrict__ qw,
                                            const float* __restrict__ qb) {
    __shared__ float smn[512], smx[512];
    __shared__ float fd[64][17];
    __shared__ float cc[2];
    __shared__ float sM[NN][17];
    __shared__ float sMM[NN];
    const int b = blockIdx.x, tid = threadIdx.x;
    const int wr = tid >> 5, l = tid & 31;

    // --- minmax over this batch ---
    float mn = 1e30f, mx = -1e30f;
    for (int t = tid; t < T; t += 512) {
        float v = x[b*T + t]; mn = fminf(mn, v); mx = fmaxf(mx, v);
    }
    smn[tid] = mn; smx[tid] = mx; __syncthreads();
    for (int o = 256; o > 0; o >>= 1) {
        if (tid < o) { smn[tid] = fminf(smn[tid], smn[tid+o]); smx[tid] = fmaxf(smx[tid], smx[tid+o]); }
        __syncthreads();
    }
    if (tid == 0) {
        cc[0] = 0.5f * (smn[0] + smx[0]);
        cc[1] = 0.5f * (smx[0] - smn[0]) + 1e-6f;
    }
    __syncthreads();
    const float c = cc[0], r = cc[1];

    // --- node values of q_h (2 passes over 1024 items) ---
#pragma unroll
    for (int k = 0; k < 2; k++) {
        int i = k*512 + tid;
        int h = i >> 4, j = i & 15;
        float xx = c + r * cospif((j + 0.5f) / (float)RR);
        fd[h][j] = QSCALE * tanhf(qw[h] * xx + qb[h]);
    }
    __syncthreads();
    // --- DCT -> per-batch coefficients ---
#pragma unroll
    for (int k = 0; k < 2; k++) {
        int i = k*512 + tid;
        int h = i >> 4, m = i & 15;
        float a = 0.0f;
        for (int j = 0; j < RR; j++)
            a += fd[h][j] * cospif((float)(m * (2*j + 1)) / (2.0f * RR));
        a *= (m == 0 ? 1.0f : 2.0f) / RR;
        g_V[b*1024 + m*64 + h] = a;
    }

    // --- u + moments ---
    float acc[NN];
#pragma unroll
    for (int n = 0; n < NN; n++) acc[n] = 0.0f;
    for (int t = tid; t < T; t += 512) {
        float u = (x[b*T + t] - c) / r;
        g_u[b*T + t] = u;
        float t0 = 1.0f, t1 = u;
        acc[0] += 1.0f; acc[1] += u;
#pragma unroll
        for (int n = 2; n < NN; n++) {
            float t2 = 2.0f*u*t1 - t0;
            acc[n] += t2;
            t0 = t1; t1 = t2;
        }
    }
#pragma unroll
    for (int n = 0; n < NN; n++) {
        float v = acc[n];
        v += __shfl_xor_sync(0xffffffff, v, 16);
        v += __shfl_xor_sync(0xffffffff, v, 8);
        v += __shfl_xor_sync(0xffffffff, v, 4);
        v += __shfl_xor_sync(0xffffffff, v, 2);
        v += __shfl_xor_sync(0xffffffff, v, 1);
        if (l == 0) sM[n][wr] = v;
    }
    __syncthreads();
    if (tid < NN) {
        float s = 0.0f;
#pragma unroll
        for (int w = 0; w < 16; w++) s += sM[tid][w];
        sMM[tid] = s;
    }
    __syncthreads();
    if (tid < NN) {
        int j = tid;
        float uj = cospif((j + 0.5f) / (float)NN);
        float t0 = 1.0f, t1 = uj;
        float w = sMM[0] * (1.0f/NN) + sMM[1] * t1 * (2.0f/NN);
        for (int n = 2; n < NN; n++) {
            float t2 = 2.0f*uj*t1 - t0;
            w += sMM[n] * t2 * (2.0f/NN);
            t0 = t1; t1 = t2;
        }
        g_wq[b*NN + j] = w;
    }
}

// =============== kv kernel: R8/R14 version (measured 95us; DO NOT TOUCH) ===============
#define KV_EA 0
#define KV_WP (64 * 66)
#define KV_U64 (2 * 64 * 66)
#define KV_SMEM (KV_U64 * 8)

__global__ __launch_bounds__(256, 2) void kv_pk(const float* __restrict__ emb,
                                                const float* __restrict__ kw,
                                                const float* __restrict__ kb,
                                                const float* __restrict__ vw) {
    extern __shared__ __align__(16) u64 sm8[];
    const int r0 = blockIdx.x * 64;
    const int tid = threadIdx.x;
    const int wr = tid >> 5, l = tid & 31;

    u64 acc[8][2] = {};

    for (int e0 = 0; e0 < E; e0 += 64) {
        __syncthreads();
#pragma unroll
        for (int k = 0; k < 4; k++) {
            int idx = k * 256 + tid;
            int r = idx & 63, eg = (idx >> 6) << 2;
            float4 v = *(const float4*)(emb + (size_t)(r0 + r) * E + e0 + eg);
            sm8[KV_EA + (eg+0)*66 + r] = pk2(v.x, v.x);
            sm8[KV_EA + (eg+1)*66 + r] = pk2(v.y, v.y);
            sm8[KV_EA + (eg+2)*66 + r] = pk2(v.z, v.z);
            sm8[KV_EA + (eg+3)*66 + r] = pk2(v.w, v.w);
        }
#pragma unroll
        for (int k = 0; k < 4; k++) {
            int idx = k * 256 + tid;
            int cp = idx & 63, eg = (idx >> 6) << 2;
            const float* w0p;
            const float* w1p;
            if (cp < 32) { w0p = kw + (size_t)(2*cp) * E; w1p = kw + (size_t)(2*cp+1) * E; }
            else         { w0p = vw + (size_t)(2*cp-64) * E; w1p = vw + (size_t)(2*cp-63) * E; }
            float4 a = *(const float4*)(w0p + e0 + eg);
            float4 bq = *(const float4*)(w1p + e0 + eg);
            sm8[KV_WP + (eg+0)*66 + cp] = pk2(a.x, bq.x);
            sm8[KV_WP + (eg+1)*66 + cp] = pk2(a.y, bq.y);
            sm8[KV_WP + (eg+2)*66 + cp] = pk2(a.z, bq.z);
            sm8[KV_WP + (eg+3)*66 + cp] = pk2(a.w, bq.w);
        }
        __syncthreads();
#pragma unroll 8
        for (int e = 0; e < 64; e++) {
            const u64* ap = sm8 + KV_EA + e*66 + 8*wr;
            ulonglong2 a01 = *(const ulonglong2*)(ap + 0);
            ulonglong2 a23 = *(const ulonglong2*)(ap + 2);
            ulonglong2 a45 = *(const ulonglong2*)(ap + 4);
            ulonglong2 a67 = *(const ulonglong2*)(ap + 6);
            u64 ar[8] = {a01.x, a01.y, a23.x, a23.y, a45.x, a45.y, a67.x, a67.y};
            ulonglong2 bb = *(const ulonglong2*)(sm8 + KV_WP + e*66 + 2*l);
#pragma unroll
            for (int j = 0; j < 8; j++) {
                ffma2(acc[j][0], ar[j], bb.x);
                ffma2(acc[j][1], ar[j], bb.y);
            }
        }
    }
    float4 bias = make_float4(0.f, 0.f, 0.f, 0.f);
    if (l < 16) bias = *(const float4*)(kb + 4*l);
#pragma unroll
    for (int j = 0; j < 8; j++) {
        float2 c01 = up2(acc[j][0]);
        float2 c23 = up2(acc[j][1]);
        size_t row = (size_t)r0 + 8*wr + j;
        float4 o;
        if (l < 16) {
            o.x = tanhf(c01.x + bias.x); o.y = tanhf(c01.y + bias.y);
            o.z = tanhf(c23.x + bias.z); o.w = tanhf(c23.y + bias.w);
            *(float4*)(g_k + row * H + 4*l) = o;
        } else {
            o.x = tanhf(c01.x); o.y = tanhf(c01.y);
            o.z = tanhf(c23.x); o.w = tanhf(c23.y);
            *(float4*)(g_v + row * H + 4*l - 64) = o;
        }
    }
}

// =============== fused attention: P -> G -> rd -> o (per 64-s block) ===============
#define AT_KS 0
#define AT_VV 0
#define AT_VS 16896
#define AT_TN 20992
#define AT_PF 25344
#define AT_GP 29696
#define AT_WS 47104
#define AT_RD 47616
#define AT_SMEM 47872

__global__ __launch_bounds__(256) void attn_k() {
    extern __shared__ __align__(16) char smb[];
    float* ks  = (float*)(smb + AT_KS);
    u64*   vv  = (u64*)  (smb + AT_VV);
    float* Vs  = (float*)(smb + AT_VS);
    float* Tn  = (float*)(smb + AT_TN);
    float* Pf  = (float*)(smb + AT_PF);
    u64*   Gp  = (u64*)  (smb + AT_GP);
    u64*   wsd = (u64*)  (smb + AT_WS);
    float* rdf = (float*)(smb + AT_RD);

    const int b = blockIdx.y, sp = blockIdx.x;
    const int s0 = sp * 64;
    const int tid = threadIdx.x, wr = tid >> 5, l = tid & 31;

#pragma unroll
    for (int k = 0; k < 4; k++) Vs[k*256 + tid] = g_V[b*1024 + k*256 + tid];
#pragma unroll
    for (int k = 0; k < 4; k++) {
        int i = k*256 + tid;
        int j = i >> 4, m = i & 15;
        Tn[j*17 + m] = cospif((float)(m * (2*j + 1)) / 128.0f);
    }
    if (tid < 64) {
        float w = g_wq[b*NN + tid];
        wsd[tid] = pk2(w, w);
    }
#pragma unroll
    for (int k = 0; k < 16; k++) {
        int i = k*256 + tid;
        int s = i >> 6, h = i & 63;
        ks[s*65 + h] = g_k[(size_t)(b*S + s0 + s)*H + h];
    }
    __syncthreads();

    {
        int s = tid & 63, mq = tid >> 6;
        float pacc[4] = {};
#pragma unroll
        for (int h = 0; h < 64; h++) {
            float kx = ks[s*65 + h];
#pragma unroll
            for (int mi = 0; mi < 4; mi++) pacc[mi] += Vs[(4*mq + mi)*64 + h] * kx;
        }
#pragma unroll
        for (int mi = 0; mi < 4; mi++) Pf[(4*mq + mi)*68 + s] = pacc[mi];
    }
    __syncthreads();

    {
        int j = tid >> 2, sq = tid & 3;
        u64 am[16];
#pragma unroll
        for (int m = 0; m < 16; m++) {
            float t = Tn[j*17 + m];
            am[m] = pk2(t, t);
        }
#pragma unroll
        for (int i = 0; i < 8; i++) {
            int p = sq + 4*i;
            u64 lacc = 0;
#pragma unroll
            for (int m = 0; m < 16; m++)
                ffma2(lacc, am[m], *(const u64*)&Pf[m*68 + 2*p]);
            float2 f = up2(lacc);
            Gp[j*34 + p] = pk2(ex2f(f.x), ex2f(f.y));
        }
    }
    __syncthreads();

    if (tid < 32) {
        int p = tid;
        u64 dacc = 0;
#pragma unroll
        for (int j = 0; j < 64; j++) ffma2(dacc, wsd[j], Gp[j*34 + p]);
        float2 d2 = up2(dacc);
        rdf[2*p]   = 1.0f / d2.x;
        rdf[2*p+1] = 1.0f / d2.y;
    }
    __syncthreads();

    {
        int p = tid >> 3, hq = tid & 7;
        size_t rv = (size_t)(b*S + s0 + 2*p) * H;
        float rd0 = rdf[2*p], rd1 = rdf[2*p+1];
#pragma unroll
        for (int i = 0; i < 8; i++) {
            int h = hq + 8*i;
            vv[p*66 + h] = pk2(g_v[rv + h] * rd0, g_v[rv + H + h] * rd1);
        }
    }
    __syncthreads();

    u64 acc[8][2] = {};
#pragma unroll 4
    for (int p = 0; p < 32; p++) {
        u64 b0 = vv[p*66 + l];
        u64 b1 = vv[p*66 + 32 + l];
#pragma unroll
        for (int jj = 0; jj < 8; jj++) {
            u64 a = Gp[(8*wr + jj)*34 + p];
            ffma2(acc[jj][0], a, b0);
            ffma2(acc[jj][1], a, b1);
        }
    }
#pragma unroll
    for (int jj = 0; jj < 8; jj++) {
        int j = 8*wr + jj;
        float2 f0 = up2(acc[jj][0]);
        float2 f1 = up2(acc[jj][1]);
        size_t base = ((size_t)(sp*B + b)*NN + j)*H;
        g_op[base + l]      = f0.x + f0.y;
        g_op[base + 32 + l] = f1.x + f1.y;
    }
}

// =============== F[b,j] = pb + sum_h pw[h] tanh( sum_sp o_partial ) ===============
__global__ __launch_bounds__(64) void ffin_k(const float* __restrict__ pw,
                                             const float* __restrict__ pb) {
    __shared__ float rs[2];
    const int b = blockIdx.y, j = blockIdx.x, h = threadIdx.x;
    float o = 0.0f;
#pragma unroll 8
    for (int sp = 0; sp < 64; sp++)
        o += g_op[((size_t)(sp*B + b)*NN + j)*H + h];
    float p = tanhf(o) * pw[h];
#pragma unroll
    for (int d = 16; d; d >>= 1) p += __shfl_xor_sync(0xffffffff, p, d);
    if ((h & 31) == 0) rs[h >> 5] = p;
    __syncthreads();
    if (h == 0) g_F[b*NN + j] = pb[0] + rs[0] + rs[1];
}

// =============== chebfit of F ===============
__global__ void cheb_k() {
    int tid = threadIdx.x;              // 256 = B*NN
    int b = tid >> 6, n = tid & 63;
    float a = 0.0f;
    for (int j = 0; j < NN; j++)
        a += g_F[b*NN + j] * cospif((float)(n * (2*j + 1)) / (2.0f * NN));
    g_a[tid] = a * ((n == 0 ? 1.0f : 2.0f) / NN);
}

// =============== out[b,t] = Clenshaw(a, u_t) ===============
__global__ __launch_bounds__(256) void final_eval(float* __restrict__ out) {
    __shared__ float as[B * NN];
    int tid = threadIdx.x;
    as[tid] = g_a[tid];
    __syncthreads();
    int i = blockIdx.x * 256 + tid;
    int b = i >> 12;
    float u = g_u[i];
    const float* a = &as[b * NN];
    float u2 = 2.0f * u;
    float bk1 = 0.0f, bk2 = 0.0f;
#pragma unroll
    for (int n = NN - 1; n >= 1; n--) {
        float bk = a[n] + u2*bk1 - bk2;
        bk2 = bk1; bk1 = bk;
    }
    out[i] = a[0] + u*bk1 - bk2;
}

// ---------------------------------------------------------------------------
extern "C" void kernel_launch(void* const* d_in, const int* in_sizes, int n_in,
                              void* d_out, int out_size) {
    const float* x   = (const float*)d_in[0];
    const float* emb = (const float*)d_in[1];
    const float* kw  = (const float*)d_in[2];
    const float* kb  = (const float*)d_in[3];
    const float* qw  = (const float*)d_in[4];
    const float* qb  = (const float*)d_in[5];
    const float* vw  = (const float*)d_in[6];
    const float* pw  = (const float*)d_in[7];
    const float* pb  = (const float*)d_in[8];
    float* out = (float*)d_out;

    cudaFuncSetAttribute(kv_pk,  cudaFuncAttributeMaxDynamicSharedMemorySize, KV_SMEM);
    cudaFuncSetAttribute(attn_k, cudaFuncAttributeMaxDynamicSharedMemorySize, AT_SMEM);

    pm_k<<<B, 512>>>(x, qw, qb);
    kv_pk<<<(B * S) / 64, 256, KV_SMEM>>>(emb, kw, kb, vw);
    attn_k<<<dim3(64, B), 256, AT_SMEM>>>();
    ffin_k<<<dim3(NN, B), 64>>>(pw, pb);
    cheb_k<<<1, 256>>>();
    final_eval<<<(B * T) / 256, 256>>>(out);
}